// round 10
// baseline (speedup 1.0000x reference)
#include <cuda_runtime.h>
#include <math_constants.h>

#define BB 4
#define NN 2048
#define IND 256
#define OUTD 256
#define HH 4
#define HD 64
#define TI 32
#define TJ 32

// ---------------- scratch ----------------
__device__ float g_Wh[BB * NN * OUTD];      // [b*N+n][h*64+d]
__device__ float g_multi[BB * NN * OUTD];
__device__ float g_ssrc[BB * HH * NN];
__device__ float g_esrP[BB * HH * NN];      // exp(s_src)
__device__ float g_esrN[BB * HH * NN];      // exp(0.2*s_src)
__device__ float4 g_pack[BB * HH * NN];     // (s_dst, exp(s_dst), exp(0.2 s_dst), 0)
__device__ float g_WcatH[IND * OUTD];       // tf32-rounded hi
__device__ float g_WcatL[IND * OUTD];       // tf32 residual lo
__device__ float g_WoutTH[OUTD * OUTD];
__device__ float g_WoutTL[OUTD * OUTD];

__device__ __forceinline__ unsigned tf32r(float x) {
    unsigned u;
    asm("cvt.rna.tf32.f32 %0, %1;" : "=r"(u) : "f"(x));
    return u;
}
__device__ __forceinline__ void cpasync16(unsigned saddr, const void* g) {
    asm volatile("cp.async.cg.shared.global [%0], [%1], 16;" :: "r"(saddr), "l"(g));
}
__device__ __forceinline__ void cpcommit() {
    asm volatile("cp.async.commit_group;" ::: "memory");
}
__device__ __forceinline__ void cpwait1() {
    asm volatile("cp.async.wait_group 1;" ::: "memory");
}
#define MMA_TF32(accv, af, b0, b1)                                              \
    asm volatile(                                                               \
        "mma.sync.aligned.m16n8k8.row.col.f32.tf32.tf32.f32 "                   \
        "{%0,%1,%2,%3}, {%4,%5,%6,%7}, {%8,%9}, {%0,%1,%2,%3};"                 \
        : "+f"(accv[0]), "+f"(accv[1]), "+f"(accv[2]), "+f"(accv[3])            \
        : "r"(af[0]), "r"(af[1]), "r"(af[2]), "r"(af[3]), "r"(b0), "r"(b1))

// ---------------- weight re-layout + tf32 hi/lo split ----------------
__global__ void transpose_kernel(const float* __restrict__ W,
                                 const float* __restrict__ Wout) {
    int idx = blockIdx.x * 256 + threadIdx.x;   // < 65536
    int k = idx >> 8, cc = idx & 255;
    int h = cc >> 6, d = cc & 63;
    float wv = W[h * (IND * HD) + k * HD + d];
    unsigned wh = tf32r(wv);
    g_WcatH[idx] = __uint_as_float(wh);
    g_WcatL[idx] = __uint_as_float(tf32r(wv - __uint_as_float(wh)));
    float ov = Wout[cc * 256 + k];
    unsigned oh = tf32r(ov);
    g_WoutTH[k * 256 + cc] = __uint_as_float(oh);
    g_WoutTL[k * 256 + cc] = __uint_as_float(tf32r(ov - __uint_as_float(oh)));
}

// ---------------- tf32x3 MMA GEMM (optionally fused s-logit epilogue) ----------------
// CTA tile 128x64, 256 thr = 8 warps (4 m x 2 n), warp tile 32x32.
__device__ __forceinline__ void mma_gemm_body(const float* __restrict__ A,
                                              const float* __restrict__ BH,
                                              const float* __restrict__ BL,
                                              float* __restrict__ C,
                                              const float* __restrict__ bias,
                                              bool has_bias,
                                              const float* __restrict__ avec) {
    __shared__ __align__(16) float As[2][128][20];
    __shared__ __align__(16) float BsH[2][16][68];
    __shared__ __align__(16) float BsL[2][16][68];
    __shared__ float aS[128];
    __shared__ float sred[2][128][2];

    int t = threadIdx.x, lane = t & 31, w = t >> 5;
    int g = lane >> 2, c = lane & 3;
    int mw = w & 3, nw = w >> 2;
    int m0 = blockIdx.y * 128, n0 = blockIdx.x * 64;
    int mb = mw * 32, nb = nw * 32;

    if (avec != nullptr && t < 128) aS[t] = avec[t];

    unsigned asb = (unsigned)__cvta_generic_to_shared(&As[0][0][0]);
    unsigned bhb = (unsigned)__cvta_generic_to_shared(&BsH[0][0][0]);
    unsigned blb = (unsigned)__cvta_generic_to_shared(&BsL[0][0][0]);

    auto stage = [&](int k0, int buf) {
#pragma unroll
        for (int q = 0; q < 2; q++) {
            int id = t + q * 256;
            int row = id >> 2, seg = id & 3;
            cpasync16(asb + buf * 10240 + row * 80 + seg * 16,
                      A + (size_t)(m0 + row) * 256 + k0 + seg * 4);
        }
        int row = t >> 4, seg = t & 15;
        cpasync16(bhb + buf * 4352 + row * 272 + seg * 16,
                  BH + (size_t)(k0 + row) * 256 + n0 + seg * 4);
        cpasync16(blb + buf * 4352 + row * 272 + seg * 16,
                  BL + (size_t)(k0 + row) * 256 + n0 + seg * 4);
    };

    float acc[2][4][4] = {};

    stage(0, 0);
    cpcommit();
    for (int s = 0; s < 16; s++) {
        int buf = s & 1;
        if (s < 15) stage((s + 1) * 16, buf ^ 1);
        cpcommit();
        cpwait1();
        __syncthreads();
#pragma unroll
        for (int kk = 0; kk < 16; kk += 8) {
            unsigned ah[2][4], al[2][4];
#pragma unroll
            for (int mi = 0; mi < 2; mi++) {
                int r0 = mb + mi * 16 + g;
#pragma unroll
                for (int q = 0; q < 4; q++) {
                    int rr = r0 + (q & 1) * 8;
                    int ck = kk + c + (q >> 1) * 4;
                    float v = As[buf][rr][ck];
                    unsigned hb = tf32r(v);
                    ah[mi][q] = hb;
                    al[mi][q] = tf32r(v - __uint_as_float(hb));
                }
            }
#pragma unroll
            for (int ni = 0; ni < 4; ni++) {
                int col = nb + ni * 8 + g;
                unsigned bh0 = __float_as_uint(BsH[buf][kk + c][col]);
                unsigned bh1 = __float_as_uint(BsH[buf][kk + c + 4][col]);
                unsigned bl0 = __float_as_uint(BsL[buf][kk + c][col]);
                unsigned bl1 = __float_as_uint(BsL[buf][kk + c + 4][col]);
#pragma unroll
                for (int mi = 0; mi < 2; mi++) {
                    MMA_TF32(acc[mi][ni], al[mi], bh0, bh1);
                    MMA_TF32(acc[mi][ni], ah[mi], bl0, bl1);
                    MMA_TF32(acc[mi][ni], ah[mi], bh0, bh1);
                }
            }
        }
        __syncthreads();
    }

#pragma unroll
    for (int mi = 0; mi < 2; mi++) {
#pragma unroll
        for (int ni = 0; ni < 4; ni++) {
            int col = n0 + nb + ni * 8 + 2 * c;
            float bx = 0.f, by = 0.f;
            if (has_bias) {
                float2 bv = *(const float2*)&bias[col];
                bx = bv.x; by = bv.y;
            }
            int r0 = m0 + mb + mi * 16 + g;
            float2 v0 = {acc[mi][ni][0] + bx, acc[mi][ni][1] + by};
            float2 v1 = {acc[mi][ni][2] + bx, acc[mi][ni][3] + by};
            *(float2*)&C[(size_t)r0 * 256 + col] = v0;
            *(float2*)&C[(size_t)(r0 + 8) * 256 + col] = v1;
        }
    }

    // ---- fused s_src/s_dst logits (gemm_wh only; n-tile == one head) ----
    if (avec != nullptr) {
        float ps[2][2] = {}, pd[2][2] = {};
#pragma unroll
        for (int mi = 0; mi < 2; mi++)
#pragma unroll
            for (int ni = 0; ni < 4; ni++) {
                int c0 = nb + ni * 8 + 2 * c;
                float as0 = aS[c0], as1 = aS[c0 + 1];
                float ad0 = aS[64 + c0], ad1 = aS[64 + c0 + 1];
                ps[mi][0] += acc[mi][ni][0] * as0 + acc[mi][ni][1] * as1;
                ps[mi][1] += acc[mi][ni][2] * as0 + acc[mi][ni][3] * as1;
                pd[mi][0] += acc[mi][ni][0] * ad0 + acc[mi][ni][1] * ad1;
                pd[mi][1] += acc[mi][ni][2] * ad0 + acc[mi][ni][3] * ad1;
            }
#pragma unroll
        for (int mi = 0; mi < 2; mi++)
#pragma unroll
            for (int rr = 0; rr < 2; rr++) {
                ps[mi][rr] += __shfl_xor_sync(0xffffffffu, ps[mi][rr], 1);
                ps[mi][rr] += __shfl_xor_sync(0xffffffffu, ps[mi][rr], 2);
                pd[mi][rr] += __shfl_xor_sync(0xffffffffu, pd[mi][rr], 1);
                pd[mi][rr] += __shfl_xor_sync(0xffffffffu, pd[mi][rr], 2);
            }
        if (c == 0) {
#pragma unroll
            for (int mi = 0; mi < 2; mi++)
#pragma unroll
                for (int rr = 0; rr < 2; rr++) {
                    int rl = mb + mi * 16 + rr * 8 + g;
                    sred[nw][rl][0] = ps[mi][rr];
                    sred[nw][rl][1] = pd[mi][rr];
                }
        }
        __syncthreads();
        if (t < 128) {
            float ss = sred[0][t][0] + sred[1][t][0];
            float sd = sred[0][t][1] + sred[1][t][1];
            int node = m0 + t;
            int bb = node >> 11, n = node & 2047;
            int hh = blockIdx.x;
            int idx = bb * (HH * NN) + hh * NN + n;
            g_ssrc[idx] = ss;
            g_esrP[idx] = __expf(ss);
            g_esrN[idx] = __expf(0.2f * ss);
            float4 pk = {sd, __expf(sd), __expf(0.2f * sd), 0.f};
            g_pack[idx] = pk;
        }
    }
}

__global__ void __launch_bounds__(256) gemm_wh(const float* __restrict__ x,
                                               const float* __restrict__ a) {
    mma_gemm_body(x, g_WcatH, g_WcatL, g_Wh, nullptr, false, a);
}
__global__ void __launch_bounds__(256) gemm_out(float* __restrict__ out,
                                                const float* __restrict__ bout) {
    mma_gemm_body(g_multi, g_WoutTH, g_WoutTL, out, bout, true, nullptr);
}

// ---------------- attention: tf32 mma, n-split warps for occupancy ----------------
// CTA: 256 thr = 8 warps. warp w: hl = w&1 (head), ns = (w>>1)&1 (col half), is = w>>2 (i-slice).
// Each warp: 16 i-rows x 32 d-cols of one head. grid (NN/32, HH/2, BB) = 512 CTAs.
__global__ void __launch_bounds__(256) attn_kernel(const int* __restrict__ adj) {
    __shared__ __align__(16) float  WhS[2][TJ][136];
    __shared__ __align__(16) int    adjS[2][TI][36];
    __shared__ float4 packS[2][2][TJ];

    int t = threadIdx.x;
    int lane = t & 31;
    int w = t >> 5;
    int hl = w & 1, ns = (w >> 1) & 1, is = w >> 2;
    int g = lane >> 2, c = lane & 3;

    int b = blockIdx.z;
    int h0 = blockIdx.y * 2;
    int i0 = blockIdx.x * TI;
    int h = h0 + hl;

    int iA = i0 + is * 16 + g;
    int sbA = b * (HH * NN) + h * NN + iA;
    float siA = g_ssrc[sbA],     ePA = g_esrP[sbA],     eNA = g_esrN[sbA];
    float siB = g_ssrc[sbA + 8], ePB = g_esrP[sbA + 8], eNB = g_esrN[sbA + 8];

    float acc[4][4];
#pragma unroll
    for (int nt = 0; nt < 4; nt++)
#pragma unroll
        for (int q = 0; q < 4; q++) acc[nt][q] = 0.f;
    float leA = 0.f, leB = 0.f;

    const float* WhB = g_Wh + (size_t)b * NN * 256 + h0 * HD;
    const int* adjB = adj + ((size_t)(b * NN + i0)) * NN;
    const float4* packB = g_pack + b * (HH * NN);

    unsigned whsb  = (unsigned)__cvta_generic_to_shared(&WhS[0][0][0]);
    unsigned adjsb = (unsigned)__cvta_generic_to_shared(&adjS[0][0][0]);
    unsigned pksb  = (unsigned)__cvta_generic_to_shared(&packS[0][0][0]);
    const unsigned WHSZ = TJ * 136 * 4, ADSZ = TI * 36 * 4, PKSZ = 2 * TJ * 16;

    int isg = is * 16 + g;
    int colb = hl * 64 + ns * 32 + g;

    auto stage = [&](int j0, int s) {
        unsigned wb = whsb + s * WHSZ;
#pragma unroll
        for (int k = 0; k < 4; k++) {
            int id = t + k * 256;                 // 1024 chunks
            int row = id >> 5, seg = id & 31;
            cpasync16(wb + row * 544 + seg * 16,
                      WhB + (size_t)(j0 + row) * 256 + seg * 4);
        }
        {
            int row = t >> 3, seg = t & 7;        // 256 chunks
            cpasync16(adjsb + s * ADSZ + row * 144 + seg * 16,
                      adjB + (size_t)row * NN + j0 + seg * 4);
        }
        if (t < 64) {
            int hh = t >> 5, jj = t & 31;
            cpasync16(pksb + s * PKSZ + t * 16,
                      packB + (h0 + hh) * NN + j0 + jj);
        }
    };

    stage(0, 0);
    cpcommit();

    for (int tile = 0; tile < NN / TJ; tile++) {
        int s = tile & 1;
        if (tile + 1 < NN / TJ) stage((tile + 1) * TJ, s ^ 1);
        cpcommit();
        cpwait1();
        __syncthreads();

#pragma unroll
        for (int kc = 0; kc < 4; kc++) {
            int j1 = kc * 8 + c, j2 = j1 + 4;
            float4 P1 = packS[s][hl][j1];
            float4 P2 = packS[s][hl][j2];
            int aA1 = adjS[s][isg][j1],     aA2 = adjS[s][isg][j2];
            int aB1 = adjS[s][isg + 8][j1], aB2 = adjS[s][isg + 8][j2];
            float e0 = (siA + P1.x > 0.f) ? ePA * P1.y : eNA * P1.z;
            float e1 = (siB + P1.x > 0.f) ? ePB * P1.y : eNB * P1.z;
            float e2 = (siA + P2.x > 0.f) ? ePA * P2.y : eNA * P2.z;
            float e3 = (siB + P2.x > 0.f) ? ePB * P2.y : eNB * P2.z;
            e0 = aA1 ? e0 : 0.f;
            e1 = aB1 ? e1 : 0.f;
            e2 = aA2 ? e2 : 0.f;
            e3 = aB2 ? e3 : 0.f;
            leA += e0 + e2;
            leB += e1 + e3;
            unsigned a0 = tf32r(e0), a1 = tf32r(e1), a2 = tf32r(e2), a3 = tf32r(e3);
            const float* r1 = &WhS[s][j1][colb];
            const float* r2 = &WhS[s][j2][colb];
#pragma unroll
            for (int nt = 0; nt < 4; nt++) {
                unsigned b0 = __float_as_uint(r1[nt * 8]);
                unsigned b1 = __float_as_uint(r2[nt * 8]);
                asm volatile(
                    "mma.sync.aligned.m16n8k8.row.col.f32.tf32.tf32.f32 "
                    "{%0,%1,%2,%3}, {%4,%5,%6,%7}, {%8,%9}, {%0,%1,%2,%3};"
                    : "+f"(acc[nt][0]), "+f"(acc[nt][1]), "+f"(acc[nt][2]), "+f"(acc[nt][3])
                    : "r"(a0), "r"(a1), "r"(a2), "r"(a3), "r"(b0), "r"(b1));
            }
        }
        __syncthreads();
    }

    leA += __shfl_xor_sync(0xffffffffu, leA, 1);
    leA += __shfl_xor_sync(0xffffffffu, leA, 2);
    leB += __shfl_xor_sync(0xffffffffu, leB, 1);
    leB += __shfl_xor_sync(0xffffffffu, leB, 2);
    float invA = 1.f / leA, invB = 1.f / leB;

    float* oA = g_multi + ((size_t)(b * NN + iA)) * 256 + hl * 64 + h0 * HD + ns * 32;
    float* oB = oA + (size_t)8 * 256;
#pragma unroll
    for (int nt = 0; nt < 4; nt++) {
        float2 vA = {acc[nt][0] * invA, acc[nt][1] * invA};
        float2 vB = {acc[nt][2] * invB, acc[nt][3] * invB};
        *(float2*)&oA[nt * 8 + 2 * c] = vA;
        *(float2*)&oB[nt * 8 + 2 * c] = vB;
    }
}

// ---------------- launch: kernel launches ONLY ----------------
extern "C" void kernel_launch(void* const* d_in, const int* in_sizes, int n_in,
                              void* d_out, int out_size) {
    const float* x    = (const float*)d_in[0];
    const int*   adj  = (const int*)d_in[1];
    const float* W    = (const float*)d_in[2];
    const float* a    = (const float*)d_in[3];
    const float* Wout = (const float*)d_in[4];
    const float* bout = (const float*)d_in[5];
    float* out = (float*)d_out;

    transpose_kernel<<<256, 256>>>(W, Wout);
    gemm_wh<<<dim3(4, 64), 256>>>(x, a);
    attn_kernel<<<dim3(NN / TI, HH / 2, BB), 256>>>(adj);
    gemm_out<<<dim3(4, 64), 256>>>(out, bout);
}

// round 11
// speedup vs baseline: 1.1702x; 1.1702x over previous
#include <cuda_runtime.h>
#include <math_constants.h>

#define BB 4
#define NN 2048
#define IND 256
#define OUTD 256
#define HH 4
#define HD 64
#define TI 32
#define TJ 32

// ---------------- scratch ----------------
__device__ float g_Wh[BB * NN * OUTD];      // [b*N+n][h*64+d]
__device__ float g_multi[BB * NN * OUTD];
__device__ float g_ssrc[BB * HH * NN];
__device__ float g_esrP[BB * HH * NN];      // exp(s_src)
__device__ float g_esrN[BB * HH * NN];      // exp(0.2*s_src)
__device__ float4 g_pack[BB * HH * NN];     // (s_dst, exp(s_dst), exp(0.2 s_dst), 0)
__device__ float g_WcatH[IND * OUTD];       // tf32-rounded hi
__device__ float g_WcatL[IND * OUTD];       // tf32 residual lo
__device__ float g_WoutTH[OUTD * OUTD];
__device__ float g_WoutTL[OUTD * OUTD];

__device__ __forceinline__ unsigned tf32r(float x) {
    unsigned u;
    asm("cvt.rna.tf32.f32 %0, %1;" : "=r"(u) : "f"(x));
    return u;
}
__device__ __forceinline__ void cpasync16(unsigned saddr, const void* g) {
    asm volatile("cp.async.cg.shared.global [%0], [%1], 16;" :: "r"(saddr), "l"(g));
}
__device__ __forceinline__ void cpcommit() {
    asm volatile("cp.async.commit_group;" ::: "memory");
}
__device__ __forceinline__ void cpwait1() {
    asm volatile("cp.async.wait_group 1;" ::: "memory");
}
#define MMA_TF32(accv, af, b0, b1)                                              \
    asm volatile(                                                               \
        "mma.sync.aligned.m16n8k8.row.col.f32.tf32.tf32.f32 "                   \
        "{%0,%1,%2,%3}, {%4,%5,%6,%7}, {%8,%9}, {%0,%1,%2,%3};"                 \
        : "+f"(accv[0]), "+f"(accv[1]), "+f"(accv[2]), "+f"(accv[3])            \
        : "r"(af[0]), "r"(af[1]), "r"(af[2]), "r"(af[3]), "r"(b0), "r"(b1))

// ---------------- weight re-layout + tf32 hi/lo split ----------------
__global__ void transpose_kernel(const float* __restrict__ W,
                                 const float* __restrict__ Wout) {
    int idx = blockIdx.x * 256 + threadIdx.x;   // < 65536
    int k = idx >> 8, cc = idx & 255;
    int h = cc >> 6, d = cc & 63;
    float wv = W[h * (IND * HD) + k * HD + d];
    unsigned wh = tf32r(wv);
    g_WcatH[idx] = __uint_as_float(wh);
    g_WcatL[idx] = __uint_as_float(tf32r(wv - __uint_as_float(wh)));
    float ov = Wout[cc * 256 + k];
    unsigned oh = tf32r(ov);
    g_WoutTH[k * 256 + cc] = __uint_as_float(oh);
    g_WoutTL[k * 256 + cc] = __uint_as_float(tf32r(ov - __uint_as_float(oh)));
}

// ---------------- tf32x3 MMA GEMM: 64x64 CTA tile, 8 warps of 16x32 ----------------
// grid (N/64=4, M/64=128) = 512 CTAs -> ~4 CTAs/SM, ~32 warps/SM.
__device__ __forceinline__ void mma_gemm_body(const float* __restrict__ A,
                                              const float* __restrict__ BH,
                                              const float* __restrict__ BL,
                                              float* __restrict__ C,
                                              const float* __restrict__ bias,
                                              bool has_bias) {
    __shared__ __align__(16) float As[2][64][20];    // frag bank = 20g+c -> distinct
    __shared__ __align__(16) float BsH[2][16][72];   // frag bank = 8c+g  -> distinct
    __shared__ __align__(16) float BsL[2][16][72];

    int t = threadIdx.x, lane = t & 31, w = t >> 5;
    int g = lane >> 2, c = lane & 3;
    int mw = w & 3, nw = w >> 2;
    int m0 = blockIdx.y * 64, n0 = blockIdx.x * 64;
    int mb = mw * 16, nb = nw * 32;

    unsigned asb = (unsigned)__cvta_generic_to_shared(&As[0][0][0]);
    unsigned bhb = (unsigned)__cvta_generic_to_shared(&BsH[0][0][0]);
    unsigned blb = (unsigned)__cvta_generic_to_shared(&BsL[0][0][0]);

    auto stage = [&](int k0, int buf) {
        {   // A: 64 rows x 16 floats = 256 chunks of 16B
            int row = t >> 2, seg = t & 3;
            cpasync16(asb + buf * 5120 + row * 80 + seg * 16,
                      A + (size_t)(m0 + row) * 256 + k0 + seg * 4);
        }
        {   // B hi/lo: 16 rows x 64 floats = 256 chunks each
            int row = t >> 4, seg = t & 15;
            cpasync16(bhb + buf * 4608 + row * 288 + seg * 16,
                      BH + (size_t)(k0 + row) * 256 + n0 + seg * 4);
            cpasync16(blb + buf * 4608 + row * 288 + seg * 16,
                      BL + (size_t)(k0 + row) * 256 + n0 + seg * 4);
        }
    };

    float acc[4][4] = {};

    stage(0, 0);
    cpcommit();
    for (int s = 0; s < 16; s++) {
        int buf = s & 1;
        if (s < 15) stage((s + 1) * 16, buf ^ 1);
        cpcommit();
        cpwait1();
        __syncthreads();
#pragma unroll
        for (int kk = 0; kk < 16; kk += 8) {
            unsigned ah[4], al[4];
#pragma unroll
            for (int q = 0; q < 4; q++) {
                int rr = mb + g + (q & 1) * 8;
                int ck = kk + c + (q >> 1) * 4;
                float v = As[buf][rr][ck];
                unsigned hb = tf32r(v);
                ah[q] = hb;
                al[q] = tf32r(v - __uint_as_float(hb));
            }
#pragma unroll
            for (int ni = 0; ni < 4; ni++) {
                int col = nb + ni * 8 + g;
                unsigned bh0 = __float_as_uint(BsH[buf][kk + c][col]);
                unsigned bh1 = __float_as_uint(BsH[buf][kk + c + 4][col]);
                unsigned bl0 = __float_as_uint(BsL[buf][kk + c][col]);
                unsigned bl1 = __float_as_uint(BsL[buf][kk + c + 4][col]);
                MMA_TF32(acc[ni], al, bh0, bh1);   // lo*hi
                MMA_TF32(acc[ni], ah, bl0, bl1);   // hi*lo
                MMA_TF32(acc[ni], ah, bh0, bh1);   // hi*hi
            }
        }
        __syncthreads();
    }

#pragma unroll
    for (int ni = 0; ni < 4; ni++) {
        int col = n0 + nb + ni * 8 + 2 * c;
        float bx = 0.f, by = 0.f;
        if (has_bias) {
            float2 bv = *(const float2*)&bias[col];
            bx = bv.x; by = bv.y;
        }
        int r0 = m0 + mb + g;
        float2 v0 = {acc[ni][0] + bx, acc[ni][1] + by};
        float2 v1 = {acc[ni][2] + bx, acc[ni][3] + by};
        *(float2*)&C[(size_t)r0 * 256 + col] = v0;
        *(float2*)&C[(size_t)(r0 + 8) * 256 + col] = v1;
    }
}

__global__ void __launch_bounds__(256, 3) gemm_wh(const float* __restrict__ x) {
    mma_gemm_body(x, g_WcatH, g_WcatL, g_Wh, nullptr, false);
}
__global__ void __launch_bounds__(256, 3) gemm_out(float* __restrict__ out,
                                                   const float* __restrict__ bout) {
    mma_gemm_body(g_multi, g_WoutTH, g_WoutTL, out, bout, true);
}

// ---------------- per-node logits + factorized exps (R9-verified) ----------------
__global__ void s_kernel(const float* __restrict__ a) {
    int idx = blockIdx.x * 256 + threadIdx.x;   // < 32768
    int b = idx >> 13;
    int r = idx & 8191;
    int h = r >> 11;
    int n = r & 2047;
    const float4* row = (const float4*)(g_Wh + ((size_t)(b * NN + n)) * 256 + h * 64);
    float ss = 0.f, sd = 0.f;
#pragma unroll
    for (int q = 0; q < 16; q++) {
        float4 v = row[q];
        float4 as = ((const float4*)a)[q];
        float4 ad = ((const float4*)(a + 64))[q];
        ss += v.x * as.x + v.y * as.y + v.z * as.z + v.w * as.w;
        sd += v.x * ad.x + v.y * ad.y + v.z * ad.z + v.w * ad.w;
    }
    g_ssrc[idx] = ss;
    g_esrP[idx] = __expf(ss);
    g_esrN[idx] = __expf(0.2f * ss);
    float4 pk;
    pk.x = sd;
    pk.y = __expf(sd);
    pk.z = __expf(0.2f * sd);
    pk.w = 0.f;
    g_pack[idx] = pk;
}

// ---------------- attention (R8/R9-verified, byte-identical) ----------------
__global__ void __launch_bounds__(128) attn_kernel(const int* __restrict__ adj) {
    __shared__ __align__(16) float  WhS[2][TJ][136];
    __shared__ __align__(16) int    adjS[2][TJ][36];
    __shared__ float4 packS[2][2][TJ];

    int t = threadIdx.x;
    int lane = t & 31;
    int w = t >> 5;
    int hl = w & 1, is = w >> 1;
    int g = lane >> 2, c = lane & 3;

    int b = blockIdx.z;
    int h0 = blockIdx.y * 2;
    int i0 = blockIdx.x * TI;
    int h = h0 + hl;

    int iA = i0 + is * 16 + g;
    int sbA = b * (HH * NN) + h * NN + iA;
    float siA = g_ssrc[sbA],     ePA = g_esrP[sbA],     eNA = g_esrN[sbA];
    float siB = g_ssrc[sbA + 8], ePB = g_esrP[sbA + 8], eNB = g_esrN[sbA + 8];

    float acc[8][4];
#pragma unroll
    for (int nt = 0; nt < 8; nt++)
#pragma unroll
        for (int q = 0; q < 4; q++) acc[nt][q] = 0.f;
    float leA = 0.f, leB = 0.f;

    const float* WhB = g_Wh + (size_t)b * NN * 256 + h0 * HD;
    const int* adjB = adj + ((size_t)(b * NN + i0)) * NN;
    const float4* packB = g_pack + b * (HH * NN);

    unsigned whsb  = (unsigned)__cvta_generic_to_shared(&WhS[0][0][0]);
    unsigned adjsb = (unsigned)__cvta_generic_to_shared(&adjS[0][0][0]);
    unsigned pksb  = (unsigned)__cvta_generic_to_shared(&packS[0][0][0]);
    const unsigned WHSZ = TJ * 136 * 4, ADSZ = TJ * 36 * 4, PKSZ = 2 * TJ * 16;

    int isg = is * 16 + g;

    auto stage = [&](int j0, int s) {
        unsigned wb = whsb + s * WHSZ;
#pragma unroll
        for (int k = 0; k < 8; k++) {
            int id = t + k * 128;
            int row = id >> 5, seg = id & 31;
            cpasync16(wb + row * 544 + seg * 16,
                      WhB + (size_t)(j0 + row) * 256 + seg * 4);
        }
        unsigned ab = adjsb + s * ADSZ;
#pragma unroll
        for (int k = 0; k < 2; k++) {
            int id = t + k * 128;
            int row = id >> 3, seg = id & 7;
            cpasync16(ab + row * 144 + seg * 16,
                      adjB + (size_t)row * NN + j0 + seg * 4);
        }
        if (t < 64) {
            int hh = t >> 5, jj = t & 31;
            cpasync16(pksb + s * PKSZ + t * 16,
                      packB + (h0 + hh) * NN + j0 + jj);
        }
    };

    stage(0, 0);
    cpcommit();

    for (int tile = 0; tile < NN / TJ; tile++) {
        int s = tile & 1;
        if (tile + 1 < NN / TJ) stage((tile + 1) * TJ, s ^ 1);
        cpcommit();
        cpwait1();
        __syncthreads();

#pragma unroll
        for (int kc = 0; kc < 4; kc++) {
            int j1 = kc * 8 + c, j2 = j1 + 4;
            float4 P1 = packS[s][hl][j1];
            float4 P2 = packS[s][hl][j2];
            int aA1 = adjS[s][isg][j1],     aA2 = adjS[s][isg][j2];
            int aB1 = adjS[s][isg + 8][j1], aB2 = adjS[s][isg + 8][j2];
            float e0 = (siA + P1.x > 0.f) ? ePA * P1.y : eNA * P1.z;
            float e1 = (siB + P1.x > 0.f) ? ePB * P1.y : eNB * P1.z;
            float e2 = (siA + P2.x > 0.f) ? ePA * P2.y : eNA * P2.z;
            float e3 = (siB + P2.x > 0.f) ? ePB * P2.y : eNB * P2.z;
            e0 = aA1 ? e0 : 0.f;
            e1 = aB1 ? e1 : 0.f;
            e2 = aA2 ? e2 : 0.f;
            e3 = aB2 ? e3 : 0.f;
            leA += e0 + e2;
            leB += e1 + e3;
            unsigned a0 = tf32r(e0), a1 = tf32r(e1), a2 = tf32r(e2), a3 = tf32r(e3);
            const float* r1 = &WhS[s][j1][hl * 64 + g];
            const float* r2 = &WhS[s][j2][hl * 64 + g];
#pragma unroll
            for (int nt = 0; nt < 8; nt++) {
                unsigned b0 = __float_as_uint(r1[nt * 8]);
                unsigned b1 = __float_as_uint(r2[nt * 8]);
                asm volatile(
                    "mma.sync.aligned.m16n8k8.row.col.f32.tf32.tf32.f32 "
                    "{%0,%1,%2,%3}, {%4,%5,%6,%7}, {%8,%9}, {%0,%1,%2,%3};"
                    : "+f"(acc[nt][0]), "+f"(acc[nt][1]), "+f"(acc[nt][2]), "+f"(acc[nt][3])
                    : "r"(a0), "r"(a1), "r"(a2), "r"(a3), "r"(b0), "r"(b1));
            }
        }
        __syncthreads();
    }

    leA += __shfl_xor_sync(0xffffffffu, leA, 1);
    leA += __shfl_xor_sync(0xffffffffu, leA, 2);
    leB += __shfl_xor_sync(0xffffffffu, leB, 1);
    leB += __shfl_xor_sync(0xffffffffu, leB, 2);
    float invA = 1.f / leA, invB = 1.f / leB;

    float* oA = g_multi + ((size_t)(b * NN + iA)) * 256 + h * HD;
    float* oB = oA + (size_t)8 * 256;
#pragma unroll
    for (int nt = 0; nt < 8; nt++) {
        float2 vA = {acc[nt][0] * invA, acc[nt][1] * invA};
        float2 vB = {acc[nt][2] * invB, acc[nt][3] * invB};
        *(float2*)&oA[nt * 8 + 2 * c] = vA;
        *(float2*)&oB[nt * 8 + 2 * c] = vB;
    }
}

// ---------------- launch: kernel launches ONLY ----------------
extern "C" void kernel_launch(void* const* d_in, const int* in_sizes, int n_in,
                              void* d_out, int out_size) {
    const float* x    = (const float*)d_in[0];
    const int*   adj  = (const int*)d_in[1];
    const float* W    = (const float*)d_in[2];
    const float* a    = (const float*)d_in[3];
    const float* Wout = (const float*)d_in[4];
    const float* bout = (const float*)d_in[5];
    float* out = (float*)d_out;

    transpose_kernel<<<256, 256>>>(W, Wout);
    gemm_wh<<<dim3(4, 128), 256>>>(x);
    s_kernel<<<128, 256>>>(a);
    attn_kernel<<<dim3(NN / TI, HH / 2, BB), 128>>>(adj);
    gemm_out<<<dim3(4, 128), 256>>>(out, bout);
}

// round 12
// speedup vs baseline: 1.2376x; 1.0576x over previous
#include <cuda_runtime.h>
#include <math_constants.h>

#define BB 4
#define NN 2048
#define IND 256
#define OUTD 256
#define HH 4
#define HD 64
#define TI 32
#define TJ 32

// ---------------- scratch ----------------
__device__ float g_Wh[BB * NN * OUTD];      // [b*N+n][h*64+d]
__device__ float g_multi[BB * NN * OUTD];
__device__ float g_part[2][BB * NN * OUTD]; // split-j partial accumulators
__device__ float g_lpart[2][BB * HH * NN];  // split-j partial row sums
__device__ float g_ssrc[BB * HH * NN];
__device__ float g_esrP[BB * HH * NN];      // exp(s_src)
__device__ float g_esrN[BB * HH * NN];      // exp(0.2*s_src)
__device__ float4 g_pack[BB * HH * NN];     // (s_dst, exp(s_dst), exp(0.2 s_dst), 0)
__device__ float g_WcatH[IND * OUTD];       // tf32-rounded hi
__device__ float g_WcatL[IND * OUTD];       // tf32 residual lo
__device__ float g_WoutTH[OUTD * OUTD];
__device__ float g_WoutTL[OUTD * OUTD];

__device__ __forceinline__ unsigned tf32r(float x) {
    unsigned u;
    asm("cvt.rna.tf32.f32 %0, %1;" : "=r"(u) : "f"(x));
    return u;
}
__device__ __forceinline__ void cpasync16(unsigned saddr, const void* g) {
    asm volatile("cp.async.cg.shared.global [%0], [%1], 16;" :: "r"(saddr), "l"(g));
}
__device__ __forceinline__ void cpcommit() {
    asm volatile("cp.async.commit_group;" ::: "memory");
}
__device__ __forceinline__ void cpwait1() {
    asm volatile("cp.async.wait_group 1;" ::: "memory");
}
#define MMA_TF32(accv, af, b0, b1)                                              \
    asm volatile(                                                               \
        "mma.sync.aligned.m16n8k8.row.col.f32.tf32.tf32.f32 "                   \
        "{%0,%1,%2,%3}, {%4,%5,%6,%7}, {%8,%9}, {%0,%1,%2,%3};"                 \
        : "+f"(accv[0]), "+f"(accv[1]), "+f"(accv[2]), "+f"(accv[3])            \
        : "r"(af[0]), "r"(af[1]), "r"(af[2]), "r"(af[3]), "r"(b0), "r"(b1))

// ---------------- weight re-layout + tf32 hi/lo split ----------------
__global__ void transpose_kernel(const float* __restrict__ W,
                                 const float* __restrict__ Wout) {
    int idx = blockIdx.x * 256 + threadIdx.x;   // < 65536
    int k = idx >> 8, cc = idx & 255;
    int h = cc >> 6, d = cc & 63;
    float wv = W[h * (IND * HD) + k * HD + d];
    unsigned wh = tf32r(wv);
    g_WcatH[idx] = __uint_as_float(wh);
    g_WcatL[idx] = __uint_as_float(tf32r(wv - __uint_as_float(wh)));
    float ov = Wout[cc * 256 + k];
    unsigned oh = tf32r(ov);
    g_WoutTH[k * 256 + cc] = __uint_as_float(oh);
    g_WoutTL[k * 256 + cc] = __uint_as_float(tf32r(ov - __uint_as_float(oh)));
}

// ---------------- tf32x3 MMA GEMM: 64x64 CTA tile (R11-verified) ----------------
__device__ __forceinline__ void mma_gemm_body(const float* __restrict__ A,
                                              const float* __restrict__ BH,
                                              const float* __restrict__ BL,
                                              float* __restrict__ C,
                                              const float* __restrict__ bias,
                                              bool has_bias) {
    __shared__ __align__(16) float As[2][64][20];
    __shared__ __align__(16) float BsH[2][16][72];
    __shared__ __align__(16) float BsL[2][16][72];

    int t = threadIdx.x, lane = t & 31, w = t >> 5;
    int g = lane >> 2, c = lane & 3;
    int mw = w & 3, nw = w >> 2;
    int m0 = blockIdx.y * 64, n0 = blockIdx.x * 64;
    int mb = mw * 16, nb = nw * 32;

    unsigned asb = (unsigned)__cvta_generic_to_shared(&As[0][0][0]);
    unsigned bhb = (unsigned)__cvta_generic_to_shared(&BsH[0][0][0]);
    unsigned blb = (unsigned)__cvta_generic_to_shared(&BsL[0][0][0]);

    auto stage = [&](int k0, int buf) {
        {
            int row = t >> 2, seg = t & 3;
            cpasync16(asb + buf * 5120 + row * 80 + seg * 16,
                      A + (size_t)(m0 + row) * 256 + k0 + seg * 4);
        }
        {
            int row = t >> 4, seg = t & 15;
            cpasync16(bhb + buf * 4608 + row * 288 + seg * 16,
                      BH + (size_t)(k0 + row) * 256 + n0 + seg * 4);
            cpasync16(blb + buf * 4608 + row * 288 + seg * 16,
                      BL + (size_t)(k0 + row) * 256 + n0 + seg * 4);
        }
    };

    float acc[4][4] = {};

    stage(0, 0);
    cpcommit();
    for (int s = 0; s < 16; s++) {
        int buf = s & 1;
        if (s < 15) stage((s + 1) * 16, buf ^ 1);
        cpcommit();
        cpwait1();
        __syncthreads();
#pragma unroll
        for (int kk = 0; kk < 16; kk += 8) {
            unsigned ah[4], al[4];
#pragma unroll
            for (int q = 0; q < 4; q++) {
                int rr = mb + g + (q & 1) * 8;
                int ck = kk + c + (q >> 1) * 4;
                float v = As[buf][rr][ck];
                unsigned hb = tf32r(v);
                ah[q] = hb;
                al[q] = tf32r(v - __uint_as_float(hb));
            }
#pragma unroll
            for (int ni = 0; ni < 4; ni++) {
                int col = nb + ni * 8 + g;
                unsigned bh0 = __float_as_uint(BsH[buf][kk + c][col]);
                unsigned bh1 = __float_as_uint(BsH[buf][kk + c + 4][col]);
                unsigned bl0 = __float_as_uint(BsL[buf][kk + c][col]);
                unsigned bl1 = __float_as_uint(BsL[buf][kk + c + 4][col]);
                MMA_TF32(acc[ni], al, bh0, bh1);
                MMA_TF32(acc[ni], ah, bl0, bl1);
                MMA_TF32(acc[ni], ah, bh0, bh1);
            }
        }
        __syncthreads();
    }

#pragma unroll
    for (int ni = 0; ni < 4; ni++) {
        int col = n0 + nb + ni * 8 + 2 * c;
        float bx = 0.f, by = 0.f;
        if (has_bias) {
            float2 bv = *(const float2*)&bias[col];
            bx = bv.x; by = bv.y;
        }
        int r0 = m0 + mb + g;
        float2 v0 = {acc[ni][0] + bx, acc[ni][1] + by};
        float2 v1 = {acc[ni][2] + bx, acc[ni][3] + by};
        *(float2*)&C[(size_t)r0 * 256 + col] = v0;
        *(float2*)&C[(size_t)(r0 + 8) * 256 + col] = v1;
    }
}

__global__ void __launch_bounds__(256, 3) gemm_wh(const float* __restrict__ x) {
    mma_gemm_body(x, g_WcatH, g_WcatL, g_Wh, nullptr, false);
}
__global__ void __launch_bounds__(256, 3) gemm_out(float* __restrict__ out,
                                                   const float* __restrict__ bout) {
    mma_gemm_body(g_multi, g_WoutTH, g_WoutTL, out, bout, true);
}

// ---------------- per-node logits + factorized exps ----------------
__global__ void s_kernel(const float* __restrict__ a) {
    int idx = blockIdx.x * 256 + threadIdx.x;   // < 32768
    int b = idx >> 13;
    int r = idx & 8191;
    int h = r >> 11;
    int n = r & 2047;
    const float4* row = (const float4*)(g_Wh + ((size_t)(b * NN + n)) * 256 + h * 64);
    float ss = 0.f, sd = 0.f;
#pragma unroll
    for (int q = 0; q < 16; q++) {
        float4 v = row[q];
        float4 as = ((const float4*)a)[q];
        float4 ad = ((const float4*)(a + 64))[q];
        ss += v.x * as.x + v.y * as.y + v.z * as.z + v.w * as.w;
        sd += v.x * ad.x + v.y * ad.y + v.z * ad.z + v.w * ad.w;
    }
    g_ssrc[idx] = ss;
    g_esrP[idx] = __expf(ss);
    g_esrN[idx] = __expf(0.2f * ss);
    float4 pk;
    pk.x = sd;
    pk.y = __expf(sd);
    pk.z = __expf(0.2f * sd);
    pk.w = 0.f;
    g_pack[idx] = pk;
}

// ---------------- attention: split-j across 2 CTAs (core logic R8-verified) ----------------
// blockIdx.z = b + BB * jhalf. Each CTA processes 32 of 64 j-tiles, writes
// UNNORMALIZED partials to g_part[jhalf] and row sums to g_lpart[jhalf].
__global__ void __launch_bounds__(128) attn_kernel(const int* __restrict__ adj) {
    __shared__ __align__(16) float  WhS[2][TJ][136];
    __shared__ __align__(16) int    adjS[2][TJ][36];
    __shared__ float4 packS[2][2][TJ];

    int t = threadIdx.x;
    int lane = t & 31;
    int w = t >> 5;
    int hl = w & 1, is = w >> 1;
    int g = lane >> 2, c = lane & 3;

    int zz = blockIdx.z;
    int b = zz & (BB - 1);
    int jh2 = zz >> 2;                      // 0/1: which j half
    int h0 = blockIdx.y * 2;
    int i0 = blockIdx.x * TI;
    int h = h0 + hl;

    int iA = i0 + is * 16 + g;
    int sbA = b * (HH * NN) + h * NN + iA;
    float siA = g_ssrc[sbA],     ePA = g_esrP[sbA],     eNA = g_esrN[sbA];
    float siB = g_ssrc[sbA + 8], ePB = g_esrP[sbA + 8], eNB = g_esrN[sbA + 8];

    float acc[8][4];
#pragma unroll
    for (int nt = 0; nt < 8; nt++)
#pragma unroll
        for (int q = 0; q < 4; q++) acc[nt][q] = 0.f;
    float leA = 0.f, leB = 0.f;

    const float* WhB = g_Wh + (size_t)b * NN * 256 + h0 * HD;
    const int* adjB = adj + ((size_t)(b * NN + i0)) * NN;
    const float4* packB = g_pack + b * (HH * NN);

    unsigned whsb  = (unsigned)__cvta_generic_to_shared(&WhS[0][0][0]);
    unsigned adjsb = (unsigned)__cvta_generic_to_shared(&adjS[0][0][0]);
    unsigned pksb  = (unsigned)__cvta_generic_to_shared(&packS[0][0][0]);
    const unsigned WHSZ = TJ * 136 * 4, ADSZ = TJ * 36 * 4, PKSZ = 2 * TJ * 16;

    int isg = is * 16 + g;
    int tile0 = jh2 * (NN / TJ / 2);        // 0 or 32
    int tile1 = tile0 + NN / TJ / 2;

    auto stage = [&](int j0, int s) {
        unsigned wb = whsb + s * WHSZ;
#pragma unroll
        for (int k = 0; k < 8; k++) {
            int id = t + k * 128;
            int row = id >> 5, seg = id & 31;
            cpasync16(wb + row * 544 + seg * 16,
                      WhB + (size_t)(j0 + row) * 256 + seg * 4);
        }
        unsigned ab = adjsb + s * ADSZ;
#pragma unroll
        for (int k = 0; k < 2; k++) {
            int id = t + k * 128;
            int row = id >> 3, seg = id & 7;
            cpasync16(ab + row * 144 + seg * 16,
                      adjB + (size_t)row * NN + j0 + seg * 4);
        }
        if (t < 64) {
            int hh = t >> 5, jj = t & 31;
            cpasync16(pksb + s * PKSZ + t * 16,
                      packB + (h0 + hh) * NN + j0 + jj);
        }
    };

    stage(tile0 * TJ, 0);
    cpcommit();

    for (int tile = tile0; tile < tile1; tile++) {
        int s = tile & 1;
        if (tile + 1 < tile1) stage((tile + 1) * TJ, s ^ 1);
        cpcommit();
        cpwait1();
        __syncthreads();

#pragma unroll
        for (int kc = 0; kc < 4; kc++) {
            int j1 = kc * 8 + c, j2 = j1 + 4;
            float4 P1 = packS[s][hl][j1];
            float4 P2 = packS[s][hl][j2];
            int aA1 = adjS[s][isg][j1],     aA2 = adjS[s][isg][j2];
            int aB1 = adjS[s][isg + 8][j1], aB2 = adjS[s][isg + 8][j2];
            float e0 = (siA + P1.x > 0.f) ? ePA * P1.y : eNA * P1.z;
            float e1 = (siB + P1.x > 0.f) ? ePB * P1.y : eNB * P1.z;
            float e2 = (siA + P2.x > 0.f) ? ePA * P2.y : eNA * P2.z;
            float e3 = (siB + P2.x > 0.f) ? ePB * P2.y : eNB * P2.z;
            e0 = aA1 ? e0 : 0.f;
            e1 = aB1 ? e1 : 0.f;
            e2 = aA2 ? e2 : 0.f;
            e3 = aB2 ? e3 : 0.f;
            leA += e0 + e2;
            leB += e1 + e3;
            unsigned a0 = tf32r(e0), a1 = tf32r(e1), a2 = tf32r(e2), a3 = tf32r(e3);
            const float* r1 = &WhS[s][j1][hl * 64 + g];
            const float* r2 = &WhS[s][j2][hl * 64 + g];
#pragma unroll
            for (int nt = 0; nt < 8; nt++) {
                unsigned b0 = __float_as_uint(r1[nt * 8]);
                unsigned b1 = __float_as_uint(r2[nt * 8]);
                asm volatile(
                    "mma.sync.aligned.m16n8k8.row.col.f32.tf32.tf32.f32 "
                    "{%0,%1,%2,%3}, {%4,%5,%6,%7}, {%8,%9}, {%0,%1,%2,%3};"
                    : "+f"(acc[nt][0]), "+f"(acc[nt][1]), "+f"(acc[nt][2]), "+f"(acc[nt][3])
                    : "r"(a0), "r"(a1), "r"(a2), "r"(a3), "r"(b0), "r"(b1));
            }
        }
        __syncthreads();
    }

    // ---- partial l sums (per-row, replicated in quad; write from c==0) ----
    leA += __shfl_xor_sync(0xffffffffu, leA, 1);
    leA += __shfl_xor_sync(0xffffffffu, leA, 2);
    leB += __shfl_xor_sync(0xffffffffu, leB, 1);
    leB += __shfl_xor_sync(0xffffffffu, leB, 2);
    if (c == 0) {
        g_lpart[jh2][sbA] = leA;
        g_lpart[jh2][sbA + 8] = leB;
    }

    // ---- unnormalized partial accumulators ----
    float* oA = g_part[jh2] + ((size_t)(b * NN + iA)) * 256 + h * HD;
    float* oB = oA + (size_t)8 * 256;
#pragma unroll
    for (int nt = 0; nt < 8; nt++) {
        float2 vA = {acc[nt][0], acc[nt][1]};
        float2 vB = {acc[nt][2], acc[nt][3]};
        *(float2*)&oA[nt * 8 + 2 * c] = vA;
        *(float2*)&oB[nt * 8 + 2 * c] = vB;
    }
}

// ---------------- combine split-j halves: multi = (p0+p1)/(l0+l1) ----------------
__global__ void reduce_kernel() {
    int idx = blockIdx.x * 256 + threadIdx.x;   // < 524288
    int e4 = idx * 4;
    int node = e4 >> 8, col = e4 & 255;
    int b = node >> 11, n = node & 2047;
    int h = col >> 6;
    int li = b * (HH * NN) + h * NN + n;
    float l = g_lpart[0][li] + g_lpart[1][li];
    float inv = 1.f / l;
    float4 p0 = *(const float4*)&g_part[0][e4];
    float4 p1 = *(const float4*)&g_part[1][e4];
    float4 o;
    o.x = (p0.x + p1.x) * inv;
    o.y = (p0.y + p1.y) * inv;
    o.z = (p0.z + p1.z) * inv;
    o.w = (p0.w + p1.w) * inv;
    *(float4*)&g_multi[e4] = o;
}

// ---------------- launch: kernel launches ONLY ----------------
extern "C" void kernel_launch(void* const* d_in, const int* in_sizes, int n_in,
                              void* d_out, int out_size) {
    const float* x    = (const float*)d_in[0];
    const int*   adj  = (const int*)d_in[1];
    const float* W    = (const float*)d_in[2];
    const float* a    = (const float*)d_in[3];
    const float* Wout = (const float*)d_in[4];
    const float* bout = (const float*)d_in[5];
    float* out = (float*)d_out;

    transpose_kernel<<<256, 256>>>(W, Wout);
    gemm_wh<<<dim3(4, 128), 256>>>(x);
    s_kernel<<<128, 256>>>(a);
    attn_kernel<<<dim3(NN / TI, HH / 2, BB * 2), 128>>>(adj);
    reduce_kernel<<<2048, 256>>>();
    gemm_out<<<dim3(4, 128), 256>>>(out, bout);
}

// round 13
// speedup vs baseline: 1.2684x; 1.0248x over previous
#include <cuda_runtime.h>
#include <math_constants.h>

#define BB 4
#define NN 2048
#define IND 256
#define OUTD 256
#define HH 4
#define HD 64
#define TI 32
#define TJ 32

// ---------------- scratch ----------------
__device__ float g_Wh[BB * NN * OUTD];      // [b*N+n][h*64+d]
__device__ float g_multi[BB * NN * OUTD];
__device__ float g_part[2][BB * NN * OUTD]; // split-j partial accumulators
__device__ float g_lpart[2][BB * HH * NN];  // split-j partial row sums
__device__ float g_ssrc[BB * HH * NN];
__device__ float g_esrP[BB * HH * NN];      // exp(s_src)
__device__ float g_esrN[BB * HH * NN];      // exp(0.2*s_src)
__device__ float4 g_pack[BB * HH * NN];     // (s_dst, exp(s_dst), exp(0.2 s_dst), 0)
__device__ float g_WcatH[IND * OUTD];       // tf32-rounded hi
__device__ float g_WcatL[IND * OUTD];       // tf32 residual lo
__device__ float g_WoutTH[OUTD * OUTD];
__device__ float g_WoutTL[OUTD * OUTD];

__device__ __forceinline__ unsigned tf32r(float x) {
    unsigned u;
    asm("cvt.rna.tf32.f32 %0, %1;" : "=r"(u) : "f"(x));
    return u;
}
__device__ __forceinline__ void cpasync16(unsigned saddr, const void* g) {
    asm volatile("cp.async.cg.shared.global [%0], [%1], 16;" :: "r"(saddr), "l"(g));
}
__device__ __forceinline__ void cpcommit() {
    asm volatile("cp.async.commit_group;" ::: "memory");
}
__device__ __forceinline__ void cpwait1() {
    asm volatile("cp.async.wait_group 1;" ::: "memory");
}
#define MMA_TF32(accv, af, b0, b1)                                              \
    asm volatile(                                                               \
        "mma.sync.aligned.m16n8k8.row.col.f32.tf32.tf32.f32 "                   \
        "{%0,%1,%2,%3}, {%4,%5,%6,%7}, {%8,%9}, {%0,%1,%2,%3};"                 \
        : "+f"(accv[0]), "+f"(accv[1]), "+f"(accv[2]), "+f"(accv[3])            \
        : "r"(af[0]), "r"(af[1]), "r"(af[2]), "r"(af[3]), "r"(b0), "r"(b1))

// ---------------- weight re-layout + tf32 hi/lo split ----------------
__global__ void transpose_kernel(const float* __restrict__ W,
                                 const float* __restrict__ Wout) {
    int idx = blockIdx.x * 256 + threadIdx.x;   // < 65536
    int k = idx >> 8, cc = idx & 255;
    int h = cc >> 6, d = cc & 63;
    float wv = W[h * (IND * HD) + k * HD + d];
    unsigned wh = tf32r(wv);
    g_WcatH[idx] = __uint_as_float(wh);
    g_WcatL[idx] = __uint_as_float(tf32r(wv - __uint_as_float(wh)));
    float ov = Wout[cc * 256 + k];
    unsigned oh = tf32r(ov);
    g_WoutTH[k * 256 + cc] = __uint_as_float(oh);
    g_WoutTL[k * 256 + cc] = __uint_as_float(tf32r(ov - __uint_as_float(oh)));
}

// ---------------- tf32x3 MMA GEMM: 64x64 CTA tile (R11-verified core) ----------------
// FUSE=true (gemm_wh): n-tile == one head; epilogue also emits s-logit tables.
template <bool FUSE>
__device__ __forceinline__ void mma_gemm_body(const float* __restrict__ A,
                                              const float* __restrict__ BH,
                                              const float* __restrict__ BL,
                                              float* __restrict__ C,
                                              const float* __restrict__ bias,
                                              bool has_bias,
                                              const float* __restrict__ avec) {
    __shared__ __align__(16) float As[2][64][20];
    __shared__ __align__(16) float BsH[2][16][72];
    __shared__ __align__(16) float BsL[2][16][72];
    __shared__ float aS[128];
    __shared__ float sred[2][64][2];

    int t = threadIdx.x, lane = t & 31, w = t >> 5;
    int g = lane >> 2, c = lane & 3;
    int mw = w & 3, nw = w >> 2;
    int m0 = blockIdx.y * 64, n0 = blockIdx.x * 64;
    int mb = mw * 16, nb = nw * 32;

    if (FUSE && t < 128) aS[t] = avec[t];

    unsigned asb = (unsigned)__cvta_generic_to_shared(&As[0][0][0]);
    unsigned bhb = (unsigned)__cvta_generic_to_shared(&BsH[0][0][0]);
    unsigned blb = (unsigned)__cvta_generic_to_shared(&BsL[0][0][0]);

    auto stage = [&](int k0, int buf) {
        {
            int row = t >> 2, seg = t & 3;
            cpasync16(asb + buf * 5120 + row * 80 + seg * 16,
                      A + (size_t)(m0 + row) * 256 + k0 + seg * 4);
        }
        {
            int row = t >> 4, seg = t & 15;
            cpasync16(bhb + buf * 4608 + row * 288 + seg * 16,
                      BH + (size_t)(k0 + row) * 256 + n0 + seg * 4);
            cpasync16(blb + buf * 4608 + row * 288 + seg * 16,
                      BL + (size_t)(k0 + row) * 256 + n0 + seg * 4);
        }
    };

    float acc[4][4] = {};

    stage(0, 0);
    cpcommit();
    for (int s = 0; s < 16; s++) {
        int buf = s & 1;
        if (s < 15) stage((s + 1) * 16, buf ^ 1);
        cpcommit();
        cpwait1();
        __syncthreads();
#pragma unroll
        for (int kk = 0; kk < 16; kk += 8) {
            unsigned ah[4], al[4];
#pragma unroll
            for (int q = 0; q < 4; q++) {
                int rr = mb + g + (q & 1) * 8;
                int ck = kk + c + (q >> 1) * 4;
                float v = As[buf][rr][ck];
                unsigned hb = tf32r(v);
                ah[q] = hb;
                al[q] = tf32r(v - __uint_as_float(hb));
            }
#pragma unroll
            for (int ni = 0; ni < 4; ni++) {
                int col = nb + ni * 8 + g;
                unsigned bh0 = __float_as_uint(BsH[buf][kk + c][col]);
                unsigned bh1 = __float_as_uint(BsH[buf][kk + c + 4][col]);
                unsigned bl0 = __float_as_uint(BsL[buf][kk + c][col]);
                unsigned bl1 = __float_as_uint(BsL[buf][kk + c + 4][col]);
                MMA_TF32(acc[ni], al, bh0, bh1);
                MMA_TF32(acc[ni], ah, bl0, bl1);
                MMA_TF32(acc[ni], ah, bh0, bh1);
            }
        }
        __syncthreads();
    }

#pragma unroll
    for (int ni = 0; ni < 4; ni++) {
        int col = n0 + nb + ni * 8 + 2 * c;
        float bx = 0.f, by = 0.f;
        if (has_bias) {
            float2 bv = *(const float2*)&bias[col];
            bx = bv.x; by = bv.y;
        }
        int r0 = m0 + mb + g;
        float2 v0 = {acc[ni][0] + bx, acc[ni][1] + by};
        float2 v1 = {acc[ni][2] + bx, acc[ni][3] + by};
        *(float2*)&C[(size_t)r0 * 256 + col] = v0;
        *(float2*)&C[(size_t)(r0 + 8) * 256 + col] = v1;
    }

    // ---- fused s-logits: this CTA's n-tile is head h = blockIdx.x ----
    if (FUSE) {
        float ps0 = 0.f, ps1 = 0.f, pd0 = 0.f, pd1 = 0.f;
#pragma unroll
        for (int ni = 0; ni < 4; ni++) {
            int c0 = nb + ni * 8 + 2 * c;          // 0..63 within head
            float as0 = aS[c0], as1 = aS[c0 + 1];
            float ad0 = aS[64 + c0], ad1 = aS[64 + c0 + 1];
            ps0 += acc[ni][0] * as0 + acc[ni][1] * as1;
            pd0 += acc[ni][0] * ad0 + acc[ni][1] * ad1;
            ps1 += acc[ni][2] * as0 + acc[ni][3] * as1;
            pd1 += acc[ni][2] * ad0 + acc[ni][3] * ad1;
        }
        ps0 += __shfl_xor_sync(0xffffffffu, ps0, 1);
        ps0 += __shfl_xor_sync(0xffffffffu, ps0, 2);
        pd0 += __shfl_xor_sync(0xffffffffu, pd0, 1);
        pd0 += __shfl_xor_sync(0xffffffffu, pd0, 2);
        ps1 += __shfl_xor_sync(0xffffffffu, ps1, 1);
        ps1 += __shfl_xor_sync(0xffffffffu, ps1, 2);
        pd1 += __shfl_xor_sync(0xffffffffu, pd1, 1);
        pd1 += __shfl_xor_sync(0xffffffffu, pd1, 2);
        if (c == 0) {
            sred[nw][mb + g][0] = ps0;
            sred[nw][mb + g][1] = pd0;
            sred[nw][mb + g + 8][0] = ps1;
            sred[nw][mb + g + 8][1] = pd1;
        }
        __syncthreads();
        if (t < 64) {
            float ss = sred[0][t][0] + sred[1][t][0];
            float sd = sred[0][t][1] + sred[1][t][1];
            int node = m0 + t;
            int b = node >> 11, n = node & 2047;
            int h = blockIdx.x;
            int idx = b * (HH * NN) + h * NN + n;
            g_ssrc[idx] = ss;
            g_esrP[idx] = __expf(ss);
            g_esrN[idx] = __expf(0.2f * ss);
            float4 pk = {sd, __expf(sd), __expf(0.2f * sd), 0.f};
            g_pack[idx] = pk;
        }
    }
}

__global__ void __launch_bounds__(256, 3) gemm_wh(const float* __restrict__ x,
                                                  const float* __restrict__ a) {
    mma_gemm_body<true>(x, g_WcatH, g_WcatL, g_Wh, nullptr, false, a);
}
__global__ void __launch_bounds__(256, 3) gemm_out(float* __restrict__ out,
                                                   const float* __restrict__ bout) {
    mma_gemm_body<false>(g_multi, g_WoutTH, g_WoutTL, out, bout, true, nullptr);
}

// ---------------- attention: split-j (R12-verified, byte-identical) ----------------
__global__ void __launch_bounds__(128) attn_kernel(const int* __restrict__ adj) {
    __shared__ __align__(16) float  WhS[2][TJ][136];
    __shared__ __align__(16) int    adjS[2][TJ][36];
    __shared__ float4 packS[2][2][TJ];

    int t = threadIdx.x;
    int lane = t & 31;
    int w = t >> 5;
    int hl = w & 1, is = w >> 1;
    int g = lane >> 2, c = lane & 3;

    int zz = blockIdx.z;
    int b = zz & (BB - 1);
    int jh2 = zz >> 2;
    int h0 = blockIdx.y * 2;
    int i0 = blockIdx.x * TI;
    int h = h0 + hl;

    int iA = i0 + is * 16 + g;
    int sbA = b * (HH * NN) + h * NN + iA;
    float siA = g_ssrc[sbA],     ePA = g_esrP[sbA],     eNA = g_esrN[sbA];
    float siB = g_ssrc[sbA + 8], ePB = g_esrP[sbA + 8], eNB = g_esrN[sbA + 8];

    float acc[8][4];
#pragma unroll
    for (int nt = 0; nt < 8; nt++)
#pragma unroll
        for (int q = 0; q < 4; q++) acc[nt][q] = 0.f;
    float leA = 0.f, leB = 0.f;

    const float* WhB = g_Wh + (size_t)b * NN * 256 + h0 * HD;
    const int* adjB = adj + ((size_t)(b * NN + i0)) * NN;
    const float4* packB = g_pack + b * (HH * NN);

    unsigned whsb  = (unsigned)__cvta_generic_to_shared(&WhS[0][0][0]);
    unsigned adjsb = (unsigned)__cvta_generic_to_shared(&adjS[0][0][0]);
    unsigned pksb  = (unsigned)__cvta_generic_to_shared(&packS[0][0][0]);
    const unsigned WHSZ = TJ * 136 * 4, ADSZ = TJ * 36 * 4, PKSZ = 2 * TJ * 16;

    int isg = is * 16 + g;
    int tile0 = jh2 * (NN / TJ / 2);
    int tile1 = tile0 + NN / TJ / 2;

    auto stage = [&](int j0, int s) {
        unsigned wb = whsb + s * WHSZ;
#pragma unroll
        for (int k = 0; k < 8; k++) {
            int id = t + k * 128;
            int row = id >> 5, seg = id & 31;
            cpasync16(wb + row * 544 + seg * 16,
                      WhB + (size_t)(j0 + row) * 256 + seg * 4);
        }
        unsigned ab = adjsb + s * ADSZ;
#pragma unroll
        for (int k = 0; k < 2; k++) {
            int id = t + k * 128;
            int row = id >> 3, seg = id & 7;
            cpasync16(ab + row * 144 + seg * 16,
                      adjB + (size_t)row * NN + j0 + seg * 4);
        }
        if (t < 64) {
            int hh = t >> 5, jj = t & 31;
            cpasync16(pksb + s * PKSZ + t * 16,
                      packB + (h0 + hh) * NN + j0 + jj);
        }
    };

    stage(tile0 * TJ, 0);
    cpcommit();

    for (int tile = tile0; tile < tile1; tile++) {
        int s = tile & 1;
        if (tile + 1 < tile1) stage((tile + 1) * TJ, s ^ 1);
        cpcommit();
        cpwait1();
        __syncthreads();

#pragma unroll
        for (int kc = 0; kc < 4; kc++) {
            int j1 = kc * 8 + c, j2 = j1 + 4;
            float4 P1 = packS[s][hl][j1];
            float4 P2 = packS[s][hl][j2];
            int aA1 = adjS[s][isg][j1],     aA2 = adjS[s][isg][j2];
            int aB1 = adjS[s][isg + 8][j1], aB2 = adjS[s][isg + 8][j2];
            float e0 = (siA + P1.x > 0.f) ? ePA * P1.y : eNA * P1.z;
            float e1 = (siB + P1.x > 0.f) ? ePB * P1.y : eNB * P1.z;
            float e2 = (siA + P2.x > 0.f) ? ePA * P2.y : eNA * P2.z;
            float e3 = (siB + P2.x > 0.f) ? ePB * P2.y : eNB * P2.z;
            e0 = aA1 ? e0 : 0.f;
            e1 = aB1 ? e1 : 0.f;
            e2 = aA2 ? e2 : 0.f;
            e3 = aB2 ? e3 : 0.f;
            leA += e0 + e2;
            leB += e1 + e3;
            unsigned a0 = tf32r(e0), a1 = tf32r(e1), a2 = tf32r(e2), a3 = tf32r(e3);
            const float* r1 = &WhS[s][j1][hl * 64 + g];
            const float* r2 = &WhS[s][j2][hl * 64 + g];
#pragma unroll
            for (int nt = 0; nt < 8; nt++) {
                unsigned b0 = __float_as_uint(r1[nt * 8]);
                unsigned b1 = __float_as_uint(r2[nt * 8]);
                asm volatile(
                    "mma.sync.aligned.m16n8k8.row.col.f32.tf32.tf32.f32 "
                    "{%0,%1,%2,%3}, {%4,%5,%6,%7}, {%8,%9}, {%0,%1,%2,%3};"
                    : "+f"(acc[nt][0]), "+f"(acc[nt][1]), "+f"(acc[nt][2]), "+f"(acc[nt][3])
                    : "r"(a0), "r"(a1), "r"(a2), "r"(a3), "r"(b0), "r"(b1));
            }
        }
        __syncthreads();
    }

    leA += __shfl_xor_sync(0xffffffffu, leA, 1);
    leA += __shfl_xor_sync(0xffffffffu, leA, 2);
    leB += __shfl_xor_sync(0xffffffffu, leB, 1);
    leB += __shfl_xor_sync(0xffffffffu, leB, 2);
    if (c == 0) {
        g_lpart[jh2][sbA] = leA;
        g_lpart[jh2][sbA + 8] = leB;
    }

    float* oA = g_part[jh2] + ((size_t)(b * NN + iA)) * 256 + h * HD;
    float* oB = oA + (size_t)8 * 256;
#pragma unroll
    for (int nt = 0; nt < 8; nt++) {
        float2 vA = {acc[nt][0], acc[nt][1]};
        float2 vB = {acc[nt][2], acc[nt][3]};
        *(float2*)&oA[nt * 8 + 2 * c] = vA;
        *(float2*)&oB[nt * 8 + 2 * c] = vB;
    }
}

// ---------------- combine split-j halves: multi = (p0+p1)/(l0+l1) ----------------
__global__ void reduce_kernel() {
    int idx = blockIdx.x * 256 + threadIdx.x;   // < 524288
    int e4 = idx * 4;
    int node = e4 >> 8, col = e4 & 255;
    int b = node >> 11, n = node & 2047;
    int h = col >> 6;
    int li = b * (HH * NN) + h * NN + n;
    float l = g_lpart[0][li] + g_lpart[1][li];
    float inv = 1.f / l;
    float4 p0 = *(const float4*)&g_part[0][e4];
    float4 p1 = *(const float4*)&g_part[1][e4];
    float4 o;
    o.x = (p0.x + p1.x) * inv;
    o.y = (p0.y + p1.y) * inv;
    o.z = (p0.z + p1.z) * inv;
    o.w = (p0.w + p1.w) * inv;
    *(float4*)&g_multi[e4] = o;
}

// ---------------- launch: kernel launches ONLY ----------------
extern "C" void kernel_launch(void* const* d_in, const int* in_sizes, int n_in,
                              void* d_out, int out_size) {
    const float* x    = (const float*)d_in[0];
    const int*   adj  = (const int*)d_in[1];
    const float* W    = (const float*)d_in[2];
    const float* a    = (const float*)d_in[3];
    const float* Wout = (const float*)d_in[4];
    const float* bout = (const float*)d_in[5];
    float* out = (float*)d_out;

    transpose_kernel<<<256, 256>>>(W, Wout);
    gemm_wh<<<dim3(4, 128), 256>>>(x, a);
    attn_kernel<<<dim3(NN / TI, HH / 2, BB * 2), 128>>>(adj);
    reduce_kernel<<<2048, 256>>>();
    gemm_out<<<dim3(4, 128), 256>>>(out, bout);
}